// round 10
// baseline (speedup 1.0000x reference)
#include <cuda_runtime.h>
#include <cuda_bf16.h>
#include <math.h>

#define N_NODES 50000
#define N_EDGES 500000
#define NFEAT   128
#define NHID    128
#define NOUT    16

// ---------------- device scratch (static allocation is allowed) ----------------
__device__ float g_deg[N_NODES];
__device__ float g_dinv[N_NODES];
__device__ int   g_count[N_NODES];
__device__ int   g_rowptr[N_NODES + 1];
__device__ int   g_fill[N_NODES];
__device__ int   g_csr_src[N_EDGES];
__device__ float g_csr_norm[N_EDGES];
__device__ float g_xw[(size_t)N_NODES * 128];   // x @ W scratch (also holds 50000x16 for layer 3)
__device__ float g_h[(size_t)N_NODES * 128];    // hidden activations

// ---------------- graph preprocessing ----------------
__global__ void init_nodes_kernel() {
    int i = blockIdx.x * blockDim.x + threadIdx.x;
    if (i < N_NODES) { g_deg[i] = 1.0f; g_count[i] = 0; }   // self-loop weight 1
}

__global__ void edge_deg_kernel(const int* __restrict__ dst, const float* __restrict__ ew) {
    int e = blockIdx.x * blockDim.x + threadIdx.x;
    if (e < N_EDGES) {
        int d = dst[e];
        atomicAdd(&g_deg[d], ew[e]);
        atomicAdd(&g_count[d], 1);
    }
}

__global__ void node_dinv_kernel() {
    int i = blockIdx.x * blockDim.x + threadIdx.x;
    if (i < N_NODES) g_dinv[i] = rsqrtf(g_deg[i]);   // deg >= 1 always
}

// single-block exclusive scan of g_count -> g_rowptr / g_fill
__global__ void scan_kernel() {
    const int T = 1024;
    const int CH = (N_NODES + T - 1) / T;   // 49
    int t = threadIdx.x;
    int s = t * CH;
    int e = min(s + CH, N_NODES);
    int local = 0;
    for (int i = s; i < e; i++) local += g_count[i];
    __shared__ int sums[T];
    sums[t] = local;
    __syncthreads();
    // Kogge-Stone inclusive scan
    for (int off = 1; off < T; off <<= 1) {
        int v = 0;
        if (t >= off) v = sums[t - off];
        __syncthreads();
        if (t >= off) sums[t] += v;
        __syncthreads();
    }
    int run = sums[t] - local;   // exclusive prefix for this chunk
    for (int i = s; i < e; i++) {
        g_rowptr[i] = run;
        g_fill[i]   = run;
        run += g_count[i];
    }
    if (t == 0) g_rowptr[N_NODES] = sums[T - 1];
}

__global__ void edge_scatter_kernel(const int* __restrict__ src, const int* __restrict__ dst,
                                    const float* __restrict__ ew) {
    int e = blockIdx.x * blockDim.x + threadIdx.x;
    if (e < N_EDGES) {
        int s = src[e], d = dst[e];
        int p = atomicAdd(&g_fill[d], 1);
        g_csr_src[p]  = s;
        g_csr_norm[p] = g_dinv[s] * ew[e] * g_dinv[d];
    }
}

// ---------------- SGEMM: [M,128] @ [128,128] -> [M,128] ----------------
__global__ __launch_bounds__(256) void gemm_f128(const float* __restrict__ A,
                                                 const float* __restrict__ W,
                                                 float* __restrict__ C, int M) {
    const int K = 128, N = 128, BM = 64, BK = 16;
    __shared__ float xs[BK][BM];   // A tile transposed
    __shared__ float ws[BK][N];
    int tid = threadIdx.x;
    int tx = tid & 15;    // col group (8 cols)
    int ty = tid >> 4;    // row group (4 rows)
    int rowBase = blockIdx.x * BM;

    float acc[4][8];
#pragma unroll
    for (int i = 0; i < 4; i++)
#pragma unroll
        for (int j = 0; j < 8; j++) acc[i][j] = 0.0f;

    int lr = tid >> 2;            // 0..63
    int lk = (tid & 3) * 4;       // 0,4,8,12
    int grow = rowBase + lr;
    bool rowOk = grow < M;
    int wkk = tid >> 4;           // 0..15
    int wnn = (tid & 15) * 8;     // 0..120

    for (int k0 = 0; k0 < K; k0 += BK) {
        float4 va = rowOk ? *(const float4*)&A[(size_t)grow * K + k0 + lk]
                          : make_float4(0.f, 0.f, 0.f, 0.f);
        xs[lk + 0][lr] = va.x; xs[lk + 1][lr] = va.y;
        xs[lk + 2][lr] = va.z; xs[lk + 3][lr] = va.w;
        const float* wp = &W[(size_t)(k0 + wkk) * N + wnn];
        float4 w0 = *(const float4*)wp;
        float4 w1 = *(const float4*)(wp + 4);
        *(float4*)&ws[wkk][wnn]     = w0;
        *(float4*)&ws[wkk][wnn + 4] = w1;
        __syncthreads();
#pragma unroll
        for (int k = 0; k < BK; k++) {
            float4 a  = *(const float4*)&xs[k][ty * 4];
            float4 b0 = *(const float4*)&ws[k][tx * 8];
            float4 b1 = *(const float4*)&ws[k][tx * 8 + 4];
            float av[4] = {a.x, a.y, a.z, a.w};
            float bv[8] = {b0.x, b0.y, b0.z, b0.w, b1.x, b1.y, b1.z, b1.w};
#pragma unroll
            for (int i = 0; i < 4; i++)
#pragma unroll
                for (int j = 0; j < 8; j++)
                    acc[i][j] = fmaf(av[i], bv[j], acc[i][j]);
        }
        __syncthreads();
    }
#pragma unroll
    for (int i = 0; i < 4; i++) {
        int r = rowBase + ty * 4 + i;
        if (r < M) {
            float4 o0 = {acc[i][0], acc[i][1], acc[i][2], acc[i][3]};
            float4 o1 = {acc[i][4], acc[i][5], acc[i][6], acc[i][7]};
            *(float4*)&C[(size_t)r * N + tx * 8]     = o0;
            *(float4*)&C[(size_t)r * N + tx * 8 + 4] = o1;
        }
    }
}

// ---------------- SGEMM: [M,128] @ [128,16] -> [M,16] ----------------
__global__ __launch_bounds__(256) void gemm_f16k(const float* __restrict__ A,
                                                 const float* __restrict__ W,
                                                 float* __restrict__ C, int M) {
    const int K = 128, N = 16, BM = 256, BK = 16;
    __shared__ float xs[BK][BM];
    __shared__ float ws[BK][N];
    int tid = threadIdx.x;
    int ty = tid >> 2;      // 0..63 -> rows ty*4..+3
    int tx = tid & 3;       // 0..3  -> cols tx*4..+3
    int rowBase = blockIdx.x * BM;
    float acc[4][4];
#pragma unroll
    for (int i = 0; i < 4; i++)
#pragma unroll
        for (int j = 0; j < 4; j++) acc[i][j] = 0.0f;

    int lr = tid >> 2;
    int lk = (tid & 3) * 4;

    for (int k0 = 0; k0 < K; k0 += BK) {
#pragma unroll
        for (int rr = 0; rr < 4; rr++) {
            int rl = lr + rr * 64;
            int row = rowBase + rl;
            float4 va = (row < M) ? *(const float4*)&A[(size_t)row * K + k0 + lk]
                                  : make_float4(0.f, 0.f, 0.f, 0.f);
            xs[lk + 0][rl] = va.x; xs[lk + 1][rl] = va.y;
            xs[lk + 2][rl] = va.z; xs[lk + 3][rl] = va.w;
        }
        if (tid < 64) {
            int kk = tid >> 2;
            int nn = (tid & 3) * 4;
            *(float4*)&ws[kk][nn] = *(const float4*)&W[(size_t)(k0 + kk) * N + nn];
        }
        __syncthreads();
#pragma unroll
        for (int k = 0; k < BK; k++) {
            float4 a = *(const float4*)&xs[k][ty * 4];
            float4 b = *(const float4*)&ws[k][tx * 4];
            float av[4] = {a.x, a.y, a.z, a.w};
            float bv[4] = {b.x, b.y, b.z, b.w};
#pragma unroll
            for (int i = 0; i < 4; i++)
#pragma unroll
                for (int j = 0; j < 4; j++)
                    acc[i][j] = fmaf(av[i], bv[j], acc[i][j]);
        }
        __syncthreads();
    }
#pragma unroll
    for (int i = 0; i < 4; i++) {
        int r = rowBase + ty * 4 + i;
        if (r < M) {
            float4 o = {acc[i][0], acc[i][1], acc[i][2], acc[i][3]};
            *(float4*)&C[(size_t)r * N + tx * 4] = o;
        }
    }
}

// ---------------- aggregation: warp per node, 128 features ----------------
__global__ __launch_bounds__(256) void agg128_kernel(const float4* __restrict__ xw,
                                                     const float* __restrict__ bias,
                                                     float4* __restrict__ out, int do_relu) {
    int gw = (blockIdx.x * blockDim.x + threadIdx.x) >> 5;
    int lane = threadIdx.x & 31;
    if (gw >= N_NODES) return;
    int i = gw;
    float di = g_dinv[i];
    float s = di * di;                         // self-loop coeff d^-1
    float4 v = xw[(size_t)i * 32 + lane];
    float4 bb = ((const float4*)bias)[lane];
    float4 acc;
    acc.x = fmaf(v.x, s, bb.x); acc.y = fmaf(v.y, s, bb.y);
    acc.z = fmaf(v.z, s, bb.z); acc.w = fmaf(v.w, s, bb.w);

    int e0 = g_rowptr[i], e1 = g_rowptr[i + 1];
    for (int eb = e0; eb < e1; eb += 32) {
        int idx = eb + lane;
        int sj = 0; float wj = 0.0f;
        if (idx < e1) { sj = g_csr_src[idx]; wj = g_csr_norm[idx]; }
        int cnt = min(32, e1 - eb);
        for (int j = 0; j < cnt; j++) {
            int   sk = __shfl_sync(0xffffffffu, sj, j);
            float wk = __shfl_sync(0xffffffffu, wj, j);
            float4 u = __ldg(&xw[(size_t)sk * 32 + lane]);
            acc.x = fmaf(wk, u.x, acc.x);
            acc.y = fmaf(wk, u.y, acc.y);
            acc.z = fmaf(wk, u.z, acc.z);
            acc.w = fmaf(wk, u.w, acc.w);
        }
    }
    if (do_relu) {
        acc.x = fmaxf(acc.x, 0.f); acc.y = fmaxf(acc.y, 0.f);
        acc.z = fmaxf(acc.z, 0.f); acc.w = fmaxf(acc.w, 0.f);
    }
    out[(size_t)i * 32 + lane] = acc;
}

// ---------------- aggregation + log_softmax: warp per node, 16 features ----------------
__global__ __launch_bounds__(256) void agg16_lsm_kernel(const float* __restrict__ xw,
                                                        const float* __restrict__ bias,
                                                        float* __restrict__ out) {
    int gw = (blockIdx.x * blockDim.x + threadIdx.x) >> 5;
    int lane = threadIdx.x & 31;
    if (gw >= N_NODES) return;
    int i = gw;
    float di = g_dinv[i];
    float s = di * di;
    float acc = 0.0f;
    if (lane < 16) acc = fmaf(xw[(size_t)i * 16 + lane], s, bias[lane]);

    int e0 = g_rowptr[i], e1 = g_rowptr[i + 1];
    for (int eb = e0; eb < e1; eb += 32) {
        int idx = eb + lane;
        int sj = 0; float wj = 0.0f;
        if (idx < e1) { sj = g_csr_src[idx]; wj = g_csr_norm[idx]; }
        int cnt = min(32, e1 - eb);
        for (int j = 0; j < cnt; j++) {
            int   sk = __shfl_sync(0xffffffffu, sj, j);
            float wk = __shfl_sync(0xffffffffu, wj, j);
            if (lane < 16)
                acc = fmaf(wk, __ldg(&xw[(size_t)sk * 16 + lane]), acc);
        }
    }
    // log_softmax across the 16 feature lanes (xor<16 keeps lanes 0-15 in-group)
    float v = (lane < 16) ? acc : -INFINITY;
    float m = v;
#pragma unroll
    for (int o = 8; o > 0; o >>= 1) m = fmaxf(m, __shfl_xor_sync(0xffffffffu, m, o));
    float ee = (lane < 16) ? expf(acc - m) : 0.0f;
    float ss = ee;
#pragma unroll
    for (int o = 8; o > 0; o >>= 1) ss += __shfl_xor_sync(0xffffffffu, ss, o);
    if (lane < 16) out[(size_t)i * 16 + lane] = acc - m - logf(ss);
}

// ---------------- launch ----------------
extern "C" void kernel_launch(void* const* d_in, const int* in_sizes, int n_in,
                              void* d_out, int out_size) {
    const float* x    = (const float*)d_in[0];
    const int*   esrc = (const int*)d_in[1];
    const int*   edst = (const int*)d_in[2];
    const float* ew   = (const float*)d_in[3];
    const float* W1   = (const float*)d_in[4];
    const float* b1   = (const float*)d_in[5];
    const float* W2   = (const float*)d_in[6];
    const float* b2   = (const float*)d_in[7];
    const float* W3   = (const float*)d_in[8];
    const float* b3   = (const float*)d_in[9];
    float* out = (float*)d_out;

    float *p_xw = nullptr, *p_h = nullptr;
    cudaGetSymbolAddress((void**)&p_xw, g_xw);
    cudaGetSymbolAddress((void**)&p_h,  g_h);

    const int NB_NODE = (N_NODES + 255) / 256;       // 196
    const int NB_EDGE = (N_EDGES + 255) / 256;       // 1954
    const int NB_WARP = (N_NODES * 32 + 255) / 256;  // 6250 (warp per node)
    const int NB_G128 = (N_NODES + 63) / 64;         // 782
    const int NB_G16  = (N_NODES + 255) / 256;       // 196

    // graph preprocessing (rebuilt every call; deterministic work)
    init_nodes_kernel<<<NB_NODE, 256>>>();
    edge_deg_kernel<<<NB_EDGE, 256>>>(edst, ew);
    node_dinv_kernel<<<NB_NODE, 256>>>();
    scan_kernel<<<1, 1024>>>();
    edge_scatter_kernel<<<NB_EDGE, 256>>>(esrc, edst, ew);

    // layer 1: h = relu(agg(x @ W1) + b1)
    gemm_f128<<<NB_G128, 256>>>(x, W1, p_xw, N_NODES);
    agg128_kernel<<<NB_WARP, 256>>>((const float4*)p_xw, b1, (float4*)p_h, 1);

    // layer 2: h = relu(agg(h @ W2) + b2)
    gemm_f128<<<NB_G128, 256>>>(p_h, W2, p_xw, N_NODES);
    agg128_kernel<<<NB_WARP, 256>>>((const float4*)p_xw, b2, (float4*)p_h, 1);

    // layer 3: out = log_softmax(agg(h @ W3) + b3)
    gemm_f16k<<<NB_G16, 256>>>(p_h, W3, p_xw, N_NODES);
    agg16_lsm_kernel<<<NB_WARP, 256>>>(p_xw, b3, out);
}

// round 11
// speedup vs baseline: 1.5162x; 1.5162x over previous
#include <cuda_runtime.h>
#include <cuda_bf16.h>
#include <math.h>

#define N_NODES 50000
#define N_EDGES 500000
#define NFEAT   128
#define NHID    128
#define NOUT    16

// ---------------- device scratch (static allocation is allowed) ----------------
__device__ float g_deg[N_NODES];
__device__ float g_dinv[N_NODES];
__device__ int   g_count[N_NODES];
__device__ int   g_rowptr[N_NODES];
__device__ int   g_fill[N_NODES];
__device__ int   g_total;
__device__ int   g_csr_src[N_EDGES];
__device__ float g_csr_norm[N_EDGES];
__device__ float g_xw[(size_t)N_NODES * 128];   // x @ W scratch (also holds 50000x16 for layer 3)
__device__ float g_h[(size_t)N_NODES * 128];    // hidden activations

// ---------------- graph preprocessing ----------------
__global__ void init_nodes_kernel() {
    int i = blockIdx.x * blockDim.x + threadIdx.x;
    if (i == 0) g_total = 0;
    if (i < N_NODES) { g_deg[i] = 1.0f; g_count[i] = 0; }   // self-loop weight 1
}

__global__ void edge_deg_kernel(const int* __restrict__ dst, const float* __restrict__ ew) {
    int e = blockIdx.x * blockDim.x + threadIdx.x;
    if (e < N_EDGES) {
        int d = dst[e];
        atomicAdd(&g_deg[d], ew[e]);
        atomicAdd(&g_count[d], 1);
    }
}

__global__ void node_dinv_kernel() {
    int i = blockIdx.x * blockDim.x + threadIdx.x;
    if (i < N_NODES) g_dinv[i] = rsqrtf(g_deg[i]);   // deg >= 1 always
}

// Segment allocation WITHOUT a global scan: each 256-node block does a local
// exclusive scan (warp shfl + smem) and grabs its base with one atomicAdd on a
// global cursor. Segments land in arbitrary block order — irrelevant, since
// each node's CSR segment is still contiguous and exact.
__global__ __launch_bounds__(256) void alloc_kernel() {
    int i = blockIdx.x * blockDim.x + threadIdx.x;
    int lane = threadIdx.x & 31, wid = threadIdx.x >> 5;
    int c = (i < N_NODES) ? g_count[i] : 0;
    // warp inclusive scan
    int p = c;
#pragma unroll
    for (int o = 1; o < 32; o <<= 1) {
        int v = __shfl_up_sync(0xffffffffu, p, o);
        if (lane >= o) p += v;
    }
    __shared__ int wsum[8];
    __shared__ int base;
    if (lane == 31) wsum[wid] = p;
    __syncthreads();
    if (threadIdx.x == 0) {
        int s = 0;
#pragma unroll
        for (int w = 0; w < 8; w++) { int t = wsum[w]; wsum[w] = s; s += t; }
        base = atomicAdd(&g_total, s);
    }
    __syncthreads();
    int off = base + wsum[wid] + (p - c);   // exclusive prefix within block + block base
    if (i < N_NODES) { g_rowptr[i] = off; g_fill[i] = off; }
}

__global__ void edge_scatter_kernel(const int* __restrict__ src, const int* __restrict__ dst,
                                    const float* __restrict__ ew) {
    int e = blockIdx.x * blockDim.x + threadIdx.x;
    if (e < N_EDGES) {
        int s = src[e], d = dst[e];
        int p = atomicAdd(&g_fill[d], 1);
        g_csr_src[p]  = s;
        g_csr_norm[p] = g_dinv[s] * ew[e] * g_dinv[d];
    }
}

// ---------------- SGEMM: [M,128] @ [128,128] -> [M,128] ----------------
// BM=128, BK=16, 256 threads, 8x8 micro-tile per thread.
__global__ __launch_bounds__(256) void gemm_f128(const float* __restrict__ A,
                                                 const float* __restrict__ W,
                                                 float* __restrict__ C, int M) {
    const int K = 128, N = 128, BM = 128, BK = 16;
    __shared__ float xs[BK][BM];   // A tile transposed
    __shared__ float ws[BK][N];
    int tid = threadIdx.x;
    int tx = tid & 15;    // col group (8 cols)
    int ty = tid >> 4;    // row group (8 rows)
    int rowBase = blockIdx.x * BM;

    float acc[8][8];
#pragma unroll
    for (int i = 0; i < 8; i++)
#pragma unroll
        for (int j = 0; j < 8; j++) acc[i][j] = 0.0f;

    int lr = tid >> 2;            // 0..63
    int lk = (tid & 3) * 4;       // 0,4,8,12
    int wkk = tid >> 4;           // 0..15
    int wnn = (tid & 15) * 8;     // 0..120

    for (int k0 = 0; k0 < K; k0 += BK) {
#pragma unroll
        for (int rr = 0; rr < 2; rr++) {
            int rl = lr + rr * 64;
            int row = rowBase + rl;
            float4 va = (row < M) ? *(const float4*)&A[(size_t)row * K + k0 + lk]
                                  : make_float4(0.f, 0.f, 0.f, 0.f);
            xs[lk + 0][rl] = va.x; xs[lk + 1][rl] = va.y;
            xs[lk + 2][rl] = va.z; xs[lk + 3][rl] = va.w;
        }
        const float* wp = &W[(size_t)(k0 + wkk) * N + wnn];
        float4 w0 = *(const float4*)wp;
        float4 w1 = *(const float4*)(wp + 4);
        *(float4*)&ws[wkk][wnn]     = w0;
        *(float4*)&ws[wkk][wnn + 4] = w1;
        __syncthreads();
#pragma unroll
        for (int k = 0; k < BK; k++) {
            float av[8], bv[8];
            *(float4*)&av[0] = *(const float4*)&xs[k][ty * 8];
            *(float4*)&av[4] = *(const float4*)&xs[k][ty * 8 + 4];
            *(float4*)&bv[0] = *(const float4*)&ws[k][tx * 8];
            *(float4*)&bv[4] = *(const float4*)&ws[k][tx * 8 + 4];
#pragma unroll
            for (int i = 0; i < 8; i++)
#pragma unroll
                for (int j = 0; j < 8; j++)
                    acc[i][j] = fmaf(av[i], bv[j], acc[i][j]);
        }
        __syncthreads();
    }
#pragma unroll
    for (int i = 0; i < 8; i++) {
        int r = rowBase + ty * 8 + i;
        if (r < M) {
            *(float4*)&C[(size_t)r * N + tx * 8]     = *(float4*)&acc[i][0];
            *(float4*)&C[(size_t)r * N + tx * 8 + 4] = *(float4*)&acc[i][4];
        }
    }
}

// ---------------- SGEMM: [M,128] @ [128,16] -> [M,16] ----------------
__global__ __launch_bounds__(256) void gemm_f16k(const float* __restrict__ A,
                                                 const float* __restrict__ W,
                                                 float* __restrict__ C, int M) {
    const int K = 128, N = 16, BM = 256, BK = 16;
    __shared__ float xs[BK][BM];
    __shared__ float ws[BK][N];
    int tid = threadIdx.x;
    int ty = tid >> 2;      // 0..63 -> rows ty*4..+3
    int tx = tid & 3;       // 0..3  -> cols tx*4..+3
    int rowBase = blockIdx.x * BM;
    float acc[4][4];
#pragma unroll
    for (int i = 0; i < 4; i++)
#pragma unroll
        for (int j = 0; j < 4; j++) acc[i][j] = 0.0f;

    int lr = tid >> 2;
    int lk = (tid & 3) * 4;

    for (int k0 = 0; k0 < K; k0 += BK) {
#pragma unroll
        for (int rr = 0; rr < 4; rr++) {
            int rl = lr + rr * 64;
            int row = rowBase + rl;
            float4 va = (row < M) ? *(const float4*)&A[(size_t)row * K + k0 + lk]
                                  : make_float4(0.f, 0.f, 0.f, 0.f);
            xs[lk + 0][rl] = va.x; xs[lk + 1][rl] = va.y;
            xs[lk + 2][rl] = va.z; xs[lk + 3][rl] = va.w;
        }
        if (tid < 64) {
            int kk = tid >> 2;
            int nn = (tid & 3) * 4;
            *(float4*)&ws[kk][nn] = *(const float4*)&W[(size_t)(k0 + kk) * N + nn];
        }
        __syncthreads();
#pragma unroll
        for (int k = 0; k < BK; k++) {
            float4 a = *(const float4*)&xs[k][ty * 4];
            float4 b = *(const float4*)&ws[k][tx * 4];
            float av[4] = {a.x, a.y, a.z, a.w};
            float bv[4] = {b.x, b.y, b.z, b.w};
#pragma unroll
            for (int i = 0; i < 4; i++)
#pragma unroll
                for (int j = 0; j < 4; j++)
                    acc[i][j] = fmaf(av[i], bv[j], acc[i][j]);
        }
        __syncthreads();
    }
#pragma unroll
    for (int i = 0; i < 4; i++) {
        int r = rowBase + ty * 4 + i;
        if (r < M) {
            float4 o = {acc[i][0], acc[i][1], acc[i][2], acc[i][3]};
            *(float4*)&C[(size_t)r * N + tx * 4] = o;
        }
    }
}

// ---------------- aggregation: warp per node, 128 features ----------------
__global__ __launch_bounds__(256) void agg128_kernel(const float4* __restrict__ xw,
                                                     const float* __restrict__ bias,
                                                     float4* __restrict__ out, int do_relu) {
    int gw = (blockIdx.x * blockDim.x + threadIdx.x) >> 5;
    int lane = threadIdx.x & 31;
    if (gw >= N_NODES) return;
    int i = gw;
    float di = g_dinv[i];
    float s = di * di;                         // self-loop coeff d^-1
    float4 v = xw[(size_t)i * 32 + lane];
    float4 bb = ((const float4*)bias)[lane];
    float4 acc;
    acc.x = fmaf(v.x, s, bb.x); acc.y = fmaf(v.y, s, bb.y);
    acc.z = fmaf(v.z, s, bb.z); acc.w = fmaf(v.w, s, bb.w);

    int e0 = g_rowptr[i], e1 = e0 + g_count[i];
    for (int eb = e0; eb < e1; eb += 32) {
        int idx = eb + lane;
        int sj = 0; float wj = 0.0f;
        if (idx < e1) { sj = g_csr_src[idx]; wj = g_csr_norm[idx]; }
        int cnt = min(32, e1 - eb);
        for (int j = 0; j < cnt; j++) {
            int   sk = __shfl_sync(0xffffffffu, sj, j);
            float wk = __shfl_sync(0xffffffffu, wj, j);
            float4 u = __ldg(&xw[(size_t)sk * 32 + lane]);
            acc.x = fmaf(wk, u.x, acc.x);
            acc.y = fmaf(wk, u.y, acc.y);
            acc.z = fmaf(wk, u.z, acc.z);
            acc.w = fmaf(wk, u.w, acc.w);
        }
    }
    if (do_relu) {
        acc.x = fmaxf(acc.x, 0.f); acc.y = fmaxf(acc.y, 0.f);
        acc.z = fmaxf(acc.z, 0.f); acc.w = fmaxf(acc.w, 0.f);
    }
    out[(size_t)i * 32 + lane] = acc;
}

// ---------------- aggregation + log_softmax: warp per node, 16 features ----------------
__global__ __launch_bounds__(256) void agg16_lsm_kernel(const float* __restrict__ xw,
                                                        const float* __restrict__ bias,
                                                        float* __restrict__ out) {
    int gw = (blockIdx.x * blockDim.x + threadIdx.x) >> 5;
    int lane = threadIdx.x & 31;
    if (gw >= N_NODES) return;
    int i = gw;
    float di = g_dinv[i];
    float s = di * di;
    float acc = 0.0f;
    if (lane < 16) acc = fmaf(xw[(size_t)i * 16 + lane], s, bias[lane]);

    int e0 = g_rowptr[i], e1 = e0 + g_count[i];
    for (int eb = e0; eb < e1; eb += 32) {
        int idx = eb + lane;
        int sj = 0; float wj = 0.0f;
        if (idx < e1) { sj = g_csr_src[idx]; wj = g_csr_norm[idx]; }
        int cnt = min(32, e1 - eb);
        for (int j = 0; j < cnt; j++) {
            int   sk = __shfl_sync(0xffffffffu, sj, j);
            float wk = __shfl_sync(0xffffffffu, wj, j);
            if (lane < 16)
                acc = fmaf(wk, __ldg(&xw[(size_t)sk * 16 + lane]), acc);
        }
    }
    // log_softmax across the 16 feature lanes (xor<16 keeps lanes 0-15 in-group)
    float v = (lane < 16) ? acc : -INFINITY;
    float m = v;
#pragma unroll
    for (int o = 8; o > 0; o >>= 1) m = fmaxf(m, __shfl_xor_sync(0xffffffffu, m, o));
    float ee = (lane < 16) ? expf(acc - m) : 0.0f;
    float ss = ee;
#pragma unroll
    for (int o = 8; o > 0; o >>= 1) ss += __shfl_xor_sync(0xffffffffu, ss, o);
    if (lane < 16) out[(size_t)i * 16 + lane] = acc - m - logf(ss);
}

// ---------------- launch ----------------
extern "C" void kernel_launch(void* const* d_in, const int* in_sizes, int n_in,
                              void* d_out, int out_size) {
    const float* x    = (const float*)d_in[0];
    const int*   esrc = (const int*)d_in[1];
    const int*   edst = (const int*)d_in[2];
    const float* ew   = (const float*)d_in[3];
    const float* W1   = (const float*)d_in[4];
    const float* b1   = (const float*)d_in[5];
    const float* W2   = (const float*)d_in[6];
    const float* b2   = (const float*)d_in[7];
    const float* W3   = (const float*)d_in[8];
    const float* b3   = (const float*)d_in[9];
    float* out = (float*)d_out;

    float *p_xw = nullptr, *p_h = nullptr;
    cudaGetSymbolAddress((void**)&p_xw, g_xw);
    cudaGetSymbolAddress((void**)&p_h,  g_h);

    const int NB_NODE = (N_NODES + 255) / 256;       // 196
    const int NB_EDGE = (N_EDGES + 255) / 256;       // 1954
    const int NB_WARP = (N_NODES * 32 + 255) / 256;  // 6250 (warp per node)
    const int NB_G128 = (N_NODES + 127) / 128;       // 391
    const int NB_G16  = (N_NODES + 255) / 256;       // 196

    // graph preprocessing (rebuilt every call; deterministic work)
    init_nodes_kernel<<<NB_NODE, 256>>>();
    edge_deg_kernel<<<NB_EDGE, 256>>>(edst, ew);
    node_dinv_kernel<<<NB_NODE, 256>>>();
    alloc_kernel<<<NB_NODE, 256>>>();
    edge_scatter_kernel<<<NB_EDGE, 256>>>(esrc, edst, ew);

    // layer 1: h = relu(agg(x @ W1) + b1)
    gemm_f128<<<NB_G128, 256>>>(x, W1, p_xw, N_NODES);
    agg128_kernel<<<NB_WARP, 256>>>((const float4*)p_xw, b1, (float4*)p_h, 1);

    // layer 2: h = relu(agg(h @ W2) + b2)
    gemm_f128<<<NB_G128, 256>>>(p_h, W2, p_xw, N_NODES);
    agg128_kernel<<<NB_WARP, 256>>>((const float4*)p_xw, b2, (float4*)p_h, 1);

    // layer 3: out = log_softmax(agg(h @ W3) + b3)
    gemm_f16k<<<NB_G16, 256>>>(p_h, W3, p_xw, N_NODES);
    agg16_lsm_kernel<<<NB_WARP, 256>>>(p_xw, b3, out);
}